// round 1
// baseline (speedup 1.0000x reference)
#include <cuda_runtime.h>
#include <math.h>

#define B_  2
#define S_  2048
#define H_  16
#define DK_ 64
#define DM_ 1024
#define M_  (B_ * S_)   // 4096

// Scratch ([B,H,S,Dk] layouts), zero-init device globals (allowed; no allocs).
__device__ float g_Q[B_ * H_ * S_ * DK_];
__device__ float g_K[B_ * H_ * S_ * DK_];
__device__ float g_V[B_ * H_ * S_ * DK_];
__device__ float g_A[B_ * H_ * S_ * DK_];

// ---------------------------------------------------------------------------
// Tiled fp32 GEMM: C[M,N] = A[M,K] @ Bw[K,N] + bias
// BM=BN=128, BK=8, 256 threads, 8x8 microtile per thread.
// MODE 0: A plain row-major; C scattered to [B,H,S,Dk] layout (QKV proj).
// MODE 1: A gathered from [B,H,S,Dk] layout; C plain row-major (O proj).
// ---------------------------------------------------------------------------
template <int MODE>
__global__ __launch_bounds__(256)
void gemm128(const float* __restrict__ A,
             const float* __restrict__ Bw,
             const float* __restrict__ bias,
             float* __restrict__ C,
             int Kdim, int Ndim)
{
    __shared__ float As[8][128];   // As[k][m]
    __shared__ float Bs[8][128];   // Bs[k][n]

    const int tid = threadIdx.x;
    const int m0 = blockIdx.y * 128;
    const int n0 = blockIdx.x * 128;
    const int ty = tid >> 4;       // 0..15
    const int tx = tid & 15;       // 0..15

    // Loader indexing
    const int arow = tid >> 1;           // 0..127
    const int akq  = (tid & 1) * 4;      // 0 or 4
    const int brow = tid >> 5;           // 0..7
    const int bnq  = (tid & 31) * 4;     // 0..124

    float acc[8][8];
#pragma unroll
    for (int i = 0; i < 8; i++)
#pragma unroll
        for (int j = 0; j < 8; j++) acc[i][j] = 0.f;

    for (int k0 = 0; k0 < Kdim; k0 += 8) {
        float4 av;
        if (MODE == 0) {
            av = *(const float4*)&A[(size_t)(m0 + arow) * Kdim + k0 + akq];
        } else {
            // Gather from [B,H,S,Dk] layout: k -> (h, d)
            int m = m0 + arow;
            int b = m >> 11;           // / S_
            int s = m & (S_ - 1);
            int k = k0 + akq;          // multiple of 4 -> same head for 4 elems
            int h = k >> 6;
            int d = k & 63;
            av = *(const float4*)&A[(((size_t)(b * H_ + h) * S_ + s) * DK_) + d];
        }
        As[akq + 0][arow] = av.x;
        As[akq + 1][arow] = av.y;
        As[akq + 2][arow] = av.z;
        As[akq + 3][arow] = av.w;

        float4 bv = *(const float4*)&Bw[(size_t)(k0 + brow) * Ndim + n0 + bnq];
        *(float4*)&Bs[brow][bnq] = bv;

        __syncthreads();

#pragma unroll
        for (int k = 0; k < 8; k++) {
            float a[8], b[8];
            *(float4*)&a[0] = *(float4*)&As[k][ty * 8];
            *(float4*)&a[4] = *(float4*)&As[k][ty * 8 + 4];
            *(float4*)&b[0] = *(float4*)&Bs[k][tx * 8];
            *(float4*)&b[4] = *(float4*)&Bs[k][tx * 8 + 4];
#pragma unroll
            for (int i = 0; i < 8; i++)
#pragma unroll
                for (int j = 0; j < 8; j++)
                    acc[i][j] = fmaf(a[i], b[j], acc[i][j]);
        }
        __syncthreads();
    }

    // Epilogue
#pragma unroll
    for (int i = 0; i < 8; i++) {
        int m = m0 + ty * 8 + i;
#pragma unroll
        for (int j = 0; j < 8; j++) {
            int n = n0 + tx * 8 + j;
            float c = acc[i][j] + bias[n];
            if (MODE == 0) {
                int b = m >> 11;
                int s = m & (S_ - 1);
                int h = n >> 6;
                int d = n & 63;
                C[((size_t)(b * H_ + h) * S_ + s) * DK_ + d] = c;
            } else {
                C[(size_t)m * Ndim + n] = c;
            }
        }
    }
}

// ---------------------------------------------------------------------------
// Flash-attention: grid (S/128, B*H), 128 threads, 1 query row per thread.
// K/V tiles of 32 keys in smem; online softmax with per-tile max via smem.
// ---------------------------------------------------------------------------
__global__ __launch_bounds__(128)
void flash_attn()
{
    __shared__ float Ks[32 * 64];    // 8 KB
    __shared__ float Vs[32 * 64];    // 8 KB
    __shared__ float Ss[32 * 128];   // 16 KB

    const int t   = threadIdx.x;
    const int bh  = blockIdx.y;
    const int row = blockIdx.x * 128 + t;

    const float scale = 0.125f;  // 1/sqrt(64)

    const float* Qp = g_Q + ((size_t)bh * S_ + row) * DK_;
    float4 q[16];
#pragma unroll
    for (int i = 0; i < 16; i++) {
        float4 v = *(const float4*)&Qp[i * 4];
        q[i] = make_float4(v.x * scale, v.y * scale, v.z * scale, v.w * scale);
    }

    float4 acc[16];
#pragma unroll
    for (int i = 0; i < 16; i++) acc[i] = make_float4(0.f, 0.f, 0.f, 0.f);

    float mrun = -1e30f;
    float l = 0.f;

    for (int kt = 0; kt < S_ / 32; kt++) {
        const float* Kg = g_K + ((size_t)bh * S_ + kt * 32) * DK_;
        const float* Vg = g_V + ((size_t)bh * S_ + kt * 32) * DK_;
#pragma unroll
        for (int r = 0; r < 4; r++) {
            int lin = r * 512 + t * 4;
            *(float4*)&Ks[lin] = *(const float4*)&Kg[lin];
            *(float4*)&Vs[lin] = *(const float4*)&Vg[lin];
        }
        __syncthreads();

        // Pass 1: scores + tile max
        float tm = -1e30f;
#pragma unroll 4
        for (int j = 0; j < 32; j++) {
            const float4* kr = (const float4*)&Ks[j * 64];
            float s0 = 0.f, s1 = 0.f, s2 = 0.f, s3 = 0.f;
#pragma unroll
            for (int i = 0; i < 16; i += 4) {
                float4 k0 = kr[i], k1 = kr[i + 1], k2 = kr[i + 2], k3 = kr[i + 3];
                s0 += q[i].x     * k0.x + q[i].y     * k0.y + q[i].z     * k0.z + q[i].w     * k0.w;
                s1 += q[i + 1].x * k1.x + q[i + 1].y * k1.y + q[i + 1].z * k1.z + q[i + 1].w * k1.w;
                s2 += q[i + 2].x * k2.x + q[i + 2].y * k2.y + q[i + 2].z * k2.z + q[i + 2].w * k2.w;
                s3 += q[i + 3].x * k3.x + q[i + 3].y * k3.y + q[i + 3].z * k3.z + q[i + 3].w * k3.w;
            }
            float sj = (s0 + s1) + (s2 + s3);
            Ss[j * 128 + t] = sj;
            tm = fmaxf(tm, sj);
        }

        // Online softmax rescale
        float mnew = fmaxf(mrun, tm);
        float corr = __expf(mrun - mnew);
        l *= corr;
#pragma unroll
        for (int i = 0; i < 16; i++) {
            acc[i].x *= corr; acc[i].y *= corr; acc[i].z *= corr; acc[i].w *= corr;
        }

        // Pass 2: accumulate P @ V
#pragma unroll 2
        for (int j = 0; j < 32; j++) {
            float p = __expf(Ss[j * 128 + t] - mnew);
            l += p;
            const float4* vr = (const float4*)&Vs[j * 64];
#pragma unroll
            for (int i = 0; i < 16; i++) {
                float4 v = vr[i];
                acc[i].x = fmaf(p, v.x, acc[i].x);
                acc[i].y = fmaf(p, v.y, acc[i].y);
                acc[i].z = fmaf(p, v.z, acc[i].z);
                acc[i].w = fmaf(p, v.w, acc[i].w);
            }
        }
        mrun = mnew;
        __syncthreads();
    }

    float inv = 1.f / l;
    float* Op = g_A + ((size_t)bh * S_ + row) * DK_;
#pragma unroll
    for (int i = 0; i < 16; i++) {
        float4 o = make_float4(acc[i].x * inv, acc[i].y * inv,
                               acc[i].z * inv, acc[i].w * inv);
        *(float4*)&Op[i * 4] = o;
    }
}

// ---------------------------------------------------------------------------
// Launch
// ---------------------------------------------------------------------------
extern "C" void kernel_launch(void* const* d_in, const int* in_sizes, int n_in,
                              void* d_out, int out_size)
{
    const float* x   = (const float*)d_in[0];
    const float* w_q = (const float*)d_in[1];
    const float* b_q = (const float*)d_in[2];
    const float* w_k = (const float*)d_in[3];
    const float* b_k = (const float*)d_in[4];
    const float* w_v = (const float*)d_in[5];
    const float* b_v = (const float*)d_in[6];
    const float* w_o = (const float*)d_in[7];
    const float* b_o = (const float*)d_in[8];
    float* out = (float*)d_out;

    float *pQ, *pK, *pV, *pA;
    cudaGetSymbolAddress((void**)&pQ, g_Q);
    cudaGetSymbolAddress((void**)&pK, g_K);
    cudaGetSymbolAddress((void**)&pV, g_V);
    cudaGetSymbolAddress((void**)&pA, g_A);

    dim3 ggrid(DM_ / 128, M_ / 128);   // (8, 32)
    dim3 gblk(256);

    gemm128<0><<<ggrid, gblk>>>(x, w_q, b_q, pQ, DM_, DM_);
    gemm128<0><<<ggrid, gblk>>>(x, w_k, b_k, pK, DM_, DM_);
    gemm128<0><<<ggrid, gblk>>>(x, w_v, b_v, pV, DM_, DM_);

    dim3 agrid(S_ / 128, B_ * H_);     // (16, 32)
    flash_attn<<<agrid, 128>>>();

    gemm128<1><<<ggrid, gblk>>>(pA, w_o, b_o, out, DM_, DM_);
}